// round 11
// baseline (speedup 1.0000x reference)
#include <cuda_runtime.h>
#include <cuda_bf16.h>

// Problem dims (fixed by the dataset)
#define Hn 256
#define Bn 128
#define Tn 1000
#define Fn 20
#define On 200
#define TPB 512          // 16 warps; 8 gather groups x 64 float4 lanes

// Preprocessed weight tables (fp32, gather-friendly row layouts). ~968 KB; L2-resident.
// g_WoT padded by 256 floats so the unconditional gather (q up to 63, j up to 255:
// float4 index q + j*50 <= 63 + 12750 = 12813 < 12864) stays in bounds.
__device__ __align__(16) float g_V1z[Hn * Hn];        // Vrec1, zero diag, [j][h]
__device__ __align__(16) float g_W2t[Hn * Hn];        // W2 transposed: [j][h] = W2[h][j]
__device__ __align__(16) float g_V2z[Hn * Hn];        // Vrec2, zero diag, [j][h]
__device__ __align__(16) float g_WoT[Hn * On + 256];  // Wout transposed: [j][o] = Wout[o][j]

// Grid MUST be exactly 256 blocks x 256 threads = 65536 = Hn*Hn. The WoT pad
// region (51200..51455) is inside that range; a larger grid would write the
// V1z/V2z/W2t lines out of bounds.
__global__ void prep_kernel(const float* __restrict__ Vrec1,
                            const float* __restrict__ W2,
                            const float* __restrict__ Vrec2,
                            const float* __restrict__ Wout) {
    int idx = blockIdx.x * 256 + threadIdx.x;   // 0..65535
    int j = idx >> 8, h = idx & 255;
    g_V1z[idx] = (j == h) ? 0.0f : Vrec1[idx];
    g_V2z[idx] = (j == h) ? 0.0f : Vrec2[idx];
    g_W2t[idx] = W2[h * Hn + j];
    if (idx < Hn * On) {
        int jj = idx / On;
        int o  = idx - jj * On;
        g_WoT[idx] = Wout[o * Hn + jj];
    } else if (idx < Hn * On + 256) {
        g_WoT[idx] = 0.0f;                      // padding (loaded, never consumed)
    }
}

// One CTA per batch element. 512 threads.
// Per step: chain A gathers {V2, Wout}·spk2[t-1]; chain B gathers {W2, V1}·spk1[t]
// (V1 partials consumed at t+1 -> latency overlapped). Output update deferred 1 step.
__global__ __launch_bounds__(TPB) void snn_kernel(
    const float* __restrict__ x,
    const float* __restrict__ W1, const float* __restrict__ b1, const float* __restrict__ beta1,
    const float* __restrict__ b2, const float* __restrict__ beta2,
    const float* __restrict__ alpha_out, const float* __restrict__ beta_out,
    float* __restrict__ out)
{
    const int tid  = threadIdx.x;
    const int b    = blockIdx.x;
    const int lane = tid & 31, warp = tid >> 5;
    const int g    = tid >> 6;        // gather group 0..7
    const int q    = tid & 63;        // float4 column lane 0..63

    __shared__ float4 pV1[TPB], pW2[TPB], pV2[TPB], pWo[TPB];   // 32 KB partials
    __shared__ unsigned short l1[Hn], l2[Hn];                   // compacted spike lists
    __shared__ unsigned sb[8];
    __shared__ float redm[8], reds[8];

    const float* pV1f = (const float*)pV1;
    const float* pW2f = (const float*)pW2;
    const float* pV2f = (const float*)pV2;
    const float* pWof = (const float*)pWo;

    // Per-neuron parameters (masked index keeps tid>=256 in-bounds)
    const int pid = tid & 255;
    float w1r[Fn];
#pragma unroll
    for (int i = 0; i < Fn; i++) w1r[i] = W1[pid * Fn + i];
    const float b1r = b1[pid], be1 = beta1[pid];
    const float b2r = b2[pid], be2 = beta2[pid];
    float aor = 0.f, bor = 0.f;
    if (tid < On) { aor = alpha_out[tid]; bor = beta_out[tid]; }

    // States
    float syn1 = 0.f, mem1 = 0.f, sp1 = 0.f;
    float syn2 = 0.f, mem2 = 0.f, sp2 = 0.f;
    float syno = 0.f, memo = 0.f, spo = 0.f, acco = 0.f;

    const float4* V1q = ((const float4*)g_V1z) + q;
    const float4* W2q = ((const float4*)g_W2t) + q;
    const float4* V2q = ((const float4*)g_V2z) + q;
    const float4* Woq = ((const float4*)g_WoT) + q;   // consumed only for q < 50; padded

    const float4* xbv = (const float4*)(x + (size_t)b * (Tn * Fn));

    // Prefetch x[0]
    float4 xr[5];
    if (tid < Hn) {
#pragma unroll
        for (int i = 0; i < 5; i++) xr[i] = __ldg(xbv + i);
    }

    // pV1 is read at t=0 before first write -> zero it
    pV1[tid] = make_float4(0.f, 0.f, 0.f, 0.f);

    int c2p = 0;            // spk2 list count (from previous step)
    __syncthreads();

    for (int t = 0; t < Tn; t++) {
        // input drive from prefetched regs; prefetch next x
        float wx = b1r;
        if (tid < Hn) {
            const float* xf = (const float*)xr;
#pragma unroll
            for (int i = 0; i < Fn; i++) wx += w1r[i] * xf[i];
            if (t + 1 < Tn) {
#pragma unroll
                for (int i = 0; i < 5; i++) xr[i] = __ldg(xbv + (t + 1) * 5 + i);
            }
        }

        // ===== chain A: gather V2·l2 and Wout·l2 (spk2[t-1]) =====
        // Unconditional fused loop: no q<50 branch (avoids intra-warp divergence
        // in odd warps). Lanes q>=50 compute unused Wout partials into pad region.
        {
            float4 a = make_float4(0.f, 0.f, 0.f, 0.f);
            float4 w = make_float4(0.f, 0.f, 0.f, 0.f);
#pragma unroll 4
            for (int k = g; k < c2p; k += 8) {
                int j = l2[k];
                float4 v = __ldg(V2q + (j << 6));
                float4 u = __ldg(Woq + j * 50);
                a.x += v.x; a.y += v.y; a.z += v.z; a.w += v.w;
                w.x += u.x; w.y += u.y; w.z += u.z; w.w += u.w;
            }
            pV2[tid] = a;
            pWo[tid] = w;
        }
        __syncthreads();                                   // A

        // ===== layer-1 neuron update (uses V1 partials gathered last step) =====
        unsigned bal = 0u;
        if (tid < Hn) {
            float r = 0.f;
#pragma unroll
            for (int gg = 0; gg < 8; gg++) r += pV1f[gg * 256 + tid];
            syn1 = 0.95f * syn1 + (wx + r);
            mem1 = be1 * mem1 + syn1 - sp1;        // detached reset: previous spike
            sp1  = (mem1 > 1.0f) ? 1.0f : 0.0f;
            bal  = __ballot_sync(0xffffffffu, sp1 > 0.5f);
            if (lane == 0) sb[warp] = bal;
        }
        // ===== deferred output update for step t-1 (uses Wout partials) =====
        float mval = -3.4e38f;
        if (tid < On && t > 0) {
            float ot = 0.f;
#pragma unroll
            for (int gg = 0; gg < 8; gg++) ot += pWof[gg * 256 + tid];
            syno = aor * syno + ot;
            memo = bor * memo + syno - spo;
            spo  = (memo > 1.0f) ? 1.0f : 0.0f;
            mval = memo;
        }
#pragma unroll
        for (int off = 16; off; off >>= 1)
            mval = fmaxf(mval, __shfl_xor_sync(0xffffffffu, mval, off));
        if (lane == 0 && warp < 8) redm[warp] = mval;
        __syncthreads();                                   // B

        // build l1[t]; start softmax
        int c1c;
        {
            int pre = 0, tot = 0;
#pragma unroll
            for (int w = 0; w < 8; w++) {
                int c = __popc(sb[w]);
                if (w < warp) pre += c;
                tot += c;
            }
            if (sp1 > 0.5f)
                l1[pre + __popc(bal & ((1u << lane) - 1u))] = (unsigned short)tid;
            c1c = tot;
        }
        float e = 0.f;
        {
            float m = redm[0];
#pragma unroll
            for (int w = 1; w < 7; w++) m = fmaxf(m, redm[w]);
            if (tid < On && t > 0) e = __expf(memo - m);
        }
        float sv = e;
#pragma unroll
        for (int off = 16; off; off >>= 1)
            sv += __shfl_xor_sync(0xffffffffu, sv, off);
        if (lane == 0 && warp < 8) reds[warp] = sv;
        __syncthreads();                                   // C

        // ===== chain B: gather W2·l1 and V1·l1 (spk1[t]); V1 -> step t+1 =====
        {
            float4 aw = make_float4(0.f, 0.f, 0.f, 0.f);
            float4 av = make_float4(0.f, 0.f, 0.f, 0.f);
#pragma unroll 4
            for (int k = g; k < c1c; k += 8) {
                int j = l1[k];
                float4 u = __ldg(W2q + (j << 6));
                float4 v = __ldg(V1q + (j << 6));
                aw.x += u.x; aw.y += u.y; aw.z += u.z; aw.w += u.w;
                av.x += v.x; av.y += v.y; av.z += v.z; av.w += v.w;
            }
            pW2[tid] = aw;
            pV1[tid] = av;
        }
        // finish softmax accumulation for t_out = t-1 (warmup: t_out > 10)
        if (tid < On && t > 11) {
            float s = reds[0];
#pragma unroll
            for (int w = 1; w < 7; w++) s += reds[w];
            acco += __fdividef(e, s);
        }
        __syncthreads();                                   // D

        // ===== layer-2 neuron update =====
        unsigned bal2 = 0u;
        if (tid < Hn) {
            float r = 0.f;
#pragma unroll
            for (int gg = 0; gg < 8; gg++)
                r += pV2f[gg * 256 + tid] + pW2f[gg * 256 + tid];
            syn2 = 0.95f * syn2 + (b2r + r);
            mem2 = be2 * mem2 + syn2 - sp2;
            sp2  = (mem2 > 1.0f) ? 1.0f : 0.0f;
            bal2 = __ballot_sync(0xffffffffu, sp2 > 0.5f);
            if (lane == 0) sb[warp] = bal2;
        }
        __syncthreads();                                   // E

        {
            int pre = 0, tot = 0;
#pragma unroll
            for (int w = 0; w < 8; w++) {
                int c = __popc(sb[w]);
                if (w < warp) pre += c;
                tot += c;
            }
            if (sp2 > 0.5f)
                l2[pre + __popc(bal2 & ((1u << lane) - 1u))] = (unsigned short)tid;
            c2p = tot;
        }
        __syncthreads();                                   // F
    }

    // ===== epilogue: output step t_out = Tn-1 =====
    {
        float4 w = make_float4(0.f, 0.f, 0.f, 0.f);
#pragma unroll 4
        for (int k = g; k < c2p; k += 8) {
            int j = l2[k];
            float4 u = __ldg(Woq + j * 50);
            w.x += u.x; w.y += u.y; w.z += u.z; w.w += u.w;
        }
        pWo[tid] = w;
    }
    __syncthreads();
    float mval = -3.4e38f;
    if (tid < On) {
        float ot = 0.f;
#pragma unroll
        for (int gg = 0; gg < 8; gg++) ot += pWof[gg * 256 + tid];
        syno = aor * syno + ot;
        memo = bor * memo + syno - spo;
        mval = memo;
    }
#pragma unroll
    for (int off = 16; off; off >>= 1)
        mval = fmaxf(mval, __shfl_xor_sync(0xffffffffu, mval, off));
    if (lane == 0 && warp < 8) redm[warp] = mval;
    __syncthreads();
    float m = redm[0];
#pragma unroll
    for (int w = 1; w < 7; w++) m = fmaxf(m, redm[w]);
    float e = (tid < On) ? __expf(memo - m) : 0.f;
    float sv = e;
#pragma unroll
    for (int off = 16; off; off >>= 1)
        sv += __shfl_xor_sync(0xffffffffu, sv, off);
    if (lane == 0 && warp < 8) reds[warp] = sv;
    __syncthreads();
    if (tid < On) {
        float s = reds[0];
#pragma unroll
        for (int w = 1; w < 7; w++) s += reds[w];
        acco += __fdividef(e, s);                // Tn-1 > 10 always
        out[b * On + tid] = acco;
    }
}

extern "C" void kernel_launch(void* const* d_in, const int* in_sizes, int n_in,
                              void* d_out, int out_size) {
    const float* x         = (const float*)d_in[0];
    const float* W1        = (const float*)d_in[1];
    const float* b1        = (const float*)d_in[2];
    const float* Vrec1     = (const float*)d_in[3];
    const float* beta1     = (const float*)d_in[4];
    const float* W2        = (const float*)d_in[5];
    const float* b2        = (const float*)d_in[6];
    const float* Vrec2     = (const float*)d_in[7];
    const float* beta2     = (const float*)d_in[8];
    const float* Wout      = (const float*)d_in[9];
    const float* alpha_out = (const float*)d_in[10];
    const float* beta_out  = (const float*)d_in[11];
    float* out = (float*)d_out;

    prep_kernel<<<256, 256>>>(Vrec1, W2, Vrec2, Wout);
    snn_kernel<<<Bn, TPB>>>(x, W1, b1, beta1, b2, beta2, alpha_out, beta_out, out);
}